// round 1
// baseline (speedup 1.0000x reference)
#include <cuda_runtime.h>
#include <math.h>

#define NN 10000
#define BB 4
#define EE 160000
#define MROWS 40000   // N*B rows

// ---------------- static scratch (no runtime allocation) ----------------
__device__ __align__(128) int   g_counts[NN + 1];
__device__ __align__(128) int   g_off[NN + 1];
__device__ __align__(128) int   g_cursor[NN];
__device__ __align__(128) int   g_csr_src[EE];
__device__ __align__(128) float g_csr_w[EE];
__device__ __align__(128) float g_X[MROWS * 128];   // packed GEMM input
__device__ __align__(128) float g_T[MROWS * 384];   // GEMM output / agg workspace
__device__ __align__(128) float g_R[MROWS * 64];    // r gate, layout [n][b][64]
__device__ __align__(128) float g_U[MROWS * 64];    // u gate, layout [n][b][64]

// ---------------- CSR build ----------------
__global__ void zero_counts_kernel() {
    int i = blockIdx.x * blockDim.x + threadIdx.x;
    if (i <= NN) g_counts[i] = 0;
}

__global__ void hist_kernel(const int* __restrict__ dst) {
    int e = blockIdx.x * blockDim.x + threadIdx.x;
    if (e < EE) atomicAdd(&g_counts[dst[e]], 1);
}

// single-block scan over 10000 counts -> exclusive offsets + cursor copy
__global__ void scan_kernel() {
    __shared__ int s[1024];
    const int t = threadIdx.x;
    const int base = t * 10;
    int vals[10];
    int run = 0;
#pragma unroll
    for (int i = 0; i < 10; i++) {
        int idx = base + i;
        int c = (idx < NN) ? g_counts[idx] : 0;
        run += c;
        vals[i] = run;
    }
    s[t] = run;
    __syncthreads();
    for (int d = 1; d < 1024; d <<= 1) {
        int v = (t >= d) ? s[t - d] : 0;
        __syncthreads();
        s[t] += v;
        __syncthreads();
    }
    int excl = s[t] - run;
    if (t == 0) g_off[0] = 0;
#pragma unroll
    for (int i = 0; i < 10; i++) {
        int idx = base + i;
        if (idx < NN) {
            g_off[idx + 1]  = excl + vals[i];
            g_cursor[idx]   = excl + (i ? vals[i - 1] : 0);
        }
    }
}

__global__ void fill_kernel(const int* __restrict__ src, const int* __restrict__ dst,
                            const float* __restrict__ ker) {
    int e = blockIdx.x * blockDim.x + threadIdx.x;
    if (e < EE) {
        int d = dst[e];
        int p = atomicAdd(&g_cursor[d], 1);
        g_csr_src[p] = src[e];
        g_csr_w[p]   = ker[e];
    }
}

// ---------------- input packing (B-major -> node-major rows of 128) ----------------
__global__ void packA_kernel(const float* __restrict__ inputs, const float* __restrict__ hx) {
    int g = blockIdx.x * blockDim.x + threadIdx.x;  // one float4 each
    if (g >= MROWS * 32) return;
    int row = g >> 5;
    int k4  = (g & 31) * 4;
    int n = row >> 2, b = row & 3;
    float4 v;
    if (k4 < 64) v = *(const float4*)&inputs[(b * NN + n) * 64 + k4];
    else         v = *(const float4*)&hx[(b * NN + n) * 64 + (k4 - 64)];
    *(float4*)&g_X[row * 128 + k4] = v;
}

__global__ void packB_kernel(const float* __restrict__ inputs, const float* __restrict__ hx) {
    int g = blockIdx.x * blockDim.x + threadIdx.x;
    if (g >= MROWS * 32) return;
    int row = g >> 5;
    int k4  = (g & 31) * 4;
    int n = row >> 2, b = row & 3;
    float4 v;
    if (k4 < 64) {
        v = *(const float4*)&inputs[(b * NN + n) * 64 + k4];
    } else {
        float4 r4 = *(const float4*)&g_R[row * 64 + (k4 - 64)];
        float4 h4 = *(const float4*)&hx[(b * NN + n) * 64 + (k4 - 64)];
        v = make_float4(r4.x * h4.x, r4.y * h4.y, r4.z * h4.z, r4.w * h4.w);
    }
    *(float4*)&g_X[row * 128 + k4] = v;
}

// ---------------- GEMM:  T[M x Ntot] = X[M x 128] @ Wcat[128 x Ntot] ----------------
// Wcat[k][v*CO + j] = W[(v*128 + k)*CO + j]   (W stored (384, CO))
template <int CO>
__global__ void gemm_kernel(const float* __restrict__ W, int Ntot) {
    __shared__ float As[16][128];
    __shared__ float Bs[16][64];
    const int tid = threadIdx.x;
    const int row0 = blockIdx.x * 128;
    const int col0 = blockIdx.y * 64;
    const int tx = tid & 15;        // 16 col-threads * 4 cols
    const int ty = tid >> 4;        // 16 row-threads * 8 rows
    float acc[8][4];
#pragma unroll
    for (int r = 0; r < 8; r++)
#pragma unroll
        for (int c = 0; c < 4; c++) acc[r][c] = 0.f;

    for (int k0 = 0; k0 < 128; k0 += 16) {
        // A tile: 128 rows x 16 k = 512 float4, 2 per thread
#pragma unroll
        for (int u = 0; u < 2; u++) {
            int lin = tid * 2 + u;
            int r = lin >> 2;
            int kq = (lin & 3) * 4;
            float4 v = make_float4(0.f, 0.f, 0.f, 0.f);
            int grow = row0 + r;
            if (grow < MROWS) v = *(const float4*)&g_X[grow * 128 + k0 + kq];
            As[kq + 0][r] = v.x;
            As[kq + 1][r] = v.y;
            As[kq + 2][r] = v.z;
            As[kq + 3][r] = v.w;
        }
        // B tile: 16 k x 64 cols = 256 float4, 1 per thread
        {
            int k  = tid >> 4;
            int jl = (tid & 15) * 4;
            int jj = col0 + jl;
            int v  = jj / CO;
            int j  = jj % CO;
            float4 w = *(const float4*)&W[(v * 128 + k0 + k) * CO + j];
            *(float4*)&Bs[k][jl] = w;
        }
        __syncthreads();
#pragma unroll
        for (int k = 0; k < 16; k++) {
            float4 bv = *(float4*)&Bs[k][tx * 4];
            float4 a0 = *(float4*)&As[k][ty * 8];
            float4 a1 = *(float4*)&As[k][ty * 8 + 4];
            float ar[8] = {a0.x, a0.y, a0.z, a0.w, a1.x, a1.y, a1.z, a1.w};
            float bc[4] = {bv.x, bv.y, bv.z, bv.w};
#pragma unroll
            for (int r = 0; r < 8; r++)
#pragma unroll
                for (int c = 0; c < 4; c++) acc[r][c] += ar[r] * bc[c];
        }
        __syncthreads();
    }
#pragma unroll
    for (int r = 0; r < 8; r++) {
        int grow = row0 + ty * 8 + r;
        if (grow < MROWS) {
            float4 o = make_float4(acc[r][0], acc[r][1], acc[r][2], acc[r][3]);
            *(float4*)&g_T[grow * Ntot + col0 + tx * 4] = o;
        }
    }
}

// ---------------- sparse aggregation: one warp per node ----------------
// acc = T[n, initOff..] + sum_edges w * T[src, srcOff..]
// MODE 0: write acc back to T[n, outOff..]
// MODE 1: (C=128) sigmoid(acc + b_ru) -> split r (j<64) / u (j>=64)
// MODE 2: (C=64)  c = tanh(acc + b_c); out = u*hx + (1-u)*c
template <int C, int MODE>
__global__ void agg_kernel(int rowStride, int srcOff, int initOff, int outOff,
                           const float* __restrict__ bias,
                           const float* __restrict__ hx,
                           float* __restrict__ out) {
    constexpr int V = (4 * C) / 128;  // float4s per lane
    const int warp = (blockIdx.x * blockDim.x + threadIdx.x) >> 5;
    const int lane = threadIdx.x & 31;
    if (warp >= NN) return;
    const int n = warp;

    int cq[V];   // per-q offset within a node row group: b*rowStride + j
    int bq[V], jq[V];
#pragma unroll
    for (int q = 0; q < V; q++) {
        int f = 4 * lane + 128 * q;
        bq[q] = f / C;
        jq[q] = f % C;
        cq[q] = bq[q] * rowStride + jq[q];
    }

    float4 acc[V];
#pragma unroll
    for (int q = 0; q < V; q++)
        acc[q] = *(const float4*)&g_T[(n * 4) * rowStride + initOff + cq[q]];

    const int beg = g_off[n];
    const int end = g_off[n + 1];
    int i = beg;
    for (; i + 1 < end; i += 2) {
        int s0 = g_csr_src[i];
        int s1 = g_csr_src[i + 1];
        float w0 = g_csr_w[i];
        float w1 = g_csr_w[i + 1];
        const float* p0 = &g_T[(s0 * 4) * rowStride + srcOff];
        const float* p1 = &g_T[(s1 * 4) * rowStride + srcOff];
        float4 v0[V], v1[V];
#pragma unroll
        for (int q = 0; q < V; q++) v0[q] = *(const float4*)&p0[cq[q]];
#pragma unroll
        for (int q = 0; q < V; q++) v1[q] = *(const float4*)&p1[cq[q]];
#pragma unroll
        for (int q = 0; q < V; q++) {
            acc[q].x += w0 * v0[q].x + w1 * v1[q].x;
            acc[q].y += w0 * v0[q].y + w1 * v1[q].y;
            acc[q].z += w0 * v0[q].z + w1 * v1[q].z;
            acc[q].w += w0 * v0[q].w + w1 * v1[q].w;
        }
    }
    if (i < end) {
        int s0 = g_csr_src[i];
        float w0 = g_csr_w[i];
        const float* p0 = &g_T[(s0 * 4) * rowStride + srcOff];
#pragma unroll
        for (int q = 0; q < V; q++) {
            float4 v = *(const float4*)&p0[cq[q]];
            acc[q].x += w0 * v.x;
            acc[q].y += w0 * v.y;
            acc[q].z += w0 * v.z;
            acc[q].w += w0 * v.w;
        }
    }

    if (MODE == 0) {
#pragma unroll
        for (int q = 0; q < V; q++)
            *(float4*)&g_T[(n * 4) * rowStride + outOff + cq[q]] = acc[q];
    } else if (MODE == 1) {
        // C=128: bq[q]=q, jq[q]=4*lane
        float4 b4 = *(const float4*)&bias[4 * lane];
#pragma unroll
        for (int q = 0; q < V; q++) {
            float4 s;
            s.x = 1.f / (1.f + expf(-(acc[q].x + b4.x)));
            s.y = 1.f / (1.f + expf(-(acc[q].y + b4.y)));
            s.z = 1.f / (1.f + expf(-(acc[q].z + b4.z)));
            s.w = 1.f / (1.f + expf(-(acc[q].w + b4.w)));
            int row = n * 4 + q;
            if (lane < 16) *(float4*)&g_R[row * 64 + 4 * lane] = s;
            else           *(float4*)&g_U[row * 64 + 4 * (lane - 16)] = s;
        }
    } else {  // MODE 2, C=64
        int j = (lane & 15) * 4;
        float4 b4 = *(const float4*)&bias[j];
#pragma unroll
        for (int q = 0; q < V; q++) {
            int b = bq[q];
            float4 c4;
            c4.x = tanhf(acc[q].x + b4.x);
            c4.y = tanhf(acc[q].y + b4.y);
            c4.z = tanhf(acc[q].z + b4.z);
            c4.w = tanhf(acc[q].w + b4.w);
            float4 u4 = *(const float4*)&g_U[(n * 4 + b) * 64 + j];
            float4 h4 = *(const float4*)&hx[(b * NN + n) * 64 + j];
            float4 o;
            o.x = u4.x * h4.x + (1.f - u4.x) * c4.x;
            o.y = u4.y * h4.y + (1.f - u4.y) * c4.y;
            o.z = u4.z * h4.z + (1.f - u4.z) * c4.z;
            o.w = u4.w * h4.w + (1.f - u4.w) * c4.w;
            *(float4*)&out[(b * NN + n) * 64 + j] = o;
        }
    }
}

// ---------------- launch ----------------
extern "C" void kernel_launch(void* const* d_in, const int* in_sizes, int n_in,
                              void* d_out, int out_size) {
    const float* inputs = (const float*)d_in[0];
    const float* hx     = (const float*)d_in[1];
    const int*   sidx   = (const int*)d_in[2];
    const float* ker    = (const float*)d_in[3];
    const float* W_ru   = (const float*)d_in[4];
    const float* b_ru   = (const float*)d_in[5];
    const float* W_c    = (const float*)d_in[6];
    const float* b_c    = (const float*)d_in[7];
    float* out = (float*)d_out;
    const int* src = sidx;
    const int* dst = sidx + EE;

    // CSR build
    zero_counts_kernel<<<(NN + 256) / 256, 256>>>();
    hist_kernel<<<(EE + 255) / 256, 256>>>(dst);
    scan_kernel<<<1, 1024>>>();
    fill_kernel<<<(EE + 255) / 256, 256>>>(src, dst, ker);

    const int packBlocks = (MROWS * 32 + 255) / 256;

    // ---- phase A: ru gates ----
    packA_kernel<<<packBlocks, 256>>>(inputs, hx);
    gemm_kernel<128><<<dim3(313, 6), 256>>>(W_ru, 384);     // T = X @ [W0|W1|W2], 40000x384
    // t1 += A t2   (cols 128..255 <- init t1, gather t2 at cols 256..383)
    agg_kernel<128, 0><<<1250, 256>>>(384, 256, 128, 128, nullptr, nullptr, nullptr);
    // ru = sigmoid(t0 + A u1 + b_ru) -> R, U
    agg_kernel<128, 1><<<1250, 256>>>(384, 128, 0, 0, b_ru, nullptr, nullptr);

    // ---- phase B: candidate + GRU mix ----
    packB_kernel<<<packBlocks, 256>>>(inputs, hx);
    gemm_kernel<64><<<dim3(313, 3), 256>>>(W_c, 192);       // T' = X' @ [W0'|W1'|W2'], 40000x192
    agg_kernel<64, 0><<<1250, 256>>>(192, 128, 64, 64, nullptr, nullptr, nullptr);
    agg_kernel<64, 2><<<1250, 256>>>(192, 64, 0, 0, b_c, hx, out);
}